// round 1
// baseline (speedup 1.0000x reference)
#include <cuda_runtime.h>
#include <cstdint>
#include <cstdio>

#define L2E 1.4426950408889634f

// Scratch (static device globals — no runtime allocation)
__device__ float g_h1[64 * 512];        // relu(f@W1+b1)
__device__ float g_P2[4 * 64 * 1024];   // split-K partials of h1@W2
__device__ float g_P3[8 * 64 * 512];    // split-K partials of h2@W3

// ---------------------------------------------------------------------------
// Generic small GEMM (M=64 fixed), computes a 128-wide K-slice partial:
//   out[m][n0+n] = sum_{k in [k0,k0+128)} Aval(m,k) * W[k*N + n]   (+bias/relu)
// Aval: either raw A[m*K_full+k], or relu(abias[k] + sum_p Aparts[p][m][k]).
// Consumer-side summation of split partials keeps everything deterministic.
// ---------------------------------------------------------------------------
__global__ __launch_bounds__(256) void gemm_part(
    const float* __restrict__ A,        // raw A or nullptr
    const float* __restrict__ Aparts,   // [nparts][64*K_full] or nullptr
    int nparts,
    const float* __restrict__ abias,    // bias for A-parts path (pre-relu)
    int K_full,
    const float* __restrict__ W, int N,
    const float* __restrict__ cbias,    // output bias or nullptr
    int do_relu,
    float* __restrict__ out)            // [splits][64*N], split = blockIdx.y
{
    __shared__ float As[64][33];
    __shared__ float Ws[32][16];

    const int tid = threadIdx.x;
    const int n0 = blockIdx.x * 16;
    const int k0 = blockIdx.y * 128;
    out += (size_t)blockIdx.y * 64 * N;

    const int n  = tid & 15;
    const int mb = (tid >> 4) * 4;
    float acc[4] = {0.f, 0.f, 0.f, 0.f};

    for (int kc = 0; kc < 128; kc += 32) {
        __syncthreads();
        // Stage A sub-chunk [64 x 32]
        #pragma unroll
        for (int it = 0; it < 8; it++) {
            int e = tid + 256 * it;
            int m = e >> 5, i = e & 31;
            int k = k0 + kc + i;
            float v;
            if (A) {
                v = A[(size_t)m * K_full + k];
            } else {
                v = abias[k];
                for (int p = 0; p < nparts; p++)
                    v += Aparts[(size_t)p * 64 * K_full + (size_t)m * K_full + k];
                v = fmaxf(v, 0.f);
            }
            As[m][i] = v;
        }
        // Stage W sub-chunk [32 x 16]
        #pragma unroll
        for (int it = 0; it < 2; it++) {
            int e = tid + 256 * it;
            int i = e >> 4, nn = e & 15;
            Ws[i][nn] = W[(size_t)(k0 + kc + i) * N + n0 + nn];
        }
        __syncthreads();
        #pragma unroll
        for (int i = 0; i < 32; i++) {
            float w = Ws[i][n];
            #pragma unroll
            for (int q = 0; q < 4; q++)
                acc[q] = fmaf(As[mb + q][i], w, acc[q]);
        }
    }

    #pragma unroll
    for (int q = 0; q < 4; q++) {
        float v = acc[q];
        if (cbias) v += cbias[n0 + n];
        if (do_relu) v = fmaxf(v, 0.f);
        out[(size_t)(mb + q) * N + n0 + n] = v;
    }
}

// ---------------------------------------------------------------------------
// Fused basis evaluation + rank-4 einsum + interleaved store.
// Grid: (8 s-chunks, 64 batches), 256 threads, 2 s-elements per thread.
// h_t[n] = ex2(p*t^2 + q*t + r) * cos(beta*t + gamma)  (log2e prefolded)
// ---------------------------------------------------------------------------
__global__ __launch_bounds__(256) void subspace_main(
    const float* __restrict__ t,
    const float* __restrict__ mu, const float* __restrict__ alpha,
    const float* __restrict__ beta, const float* __restrict__ gamma,
    const float* __restrict__ b3,
    float* __restrict__ out)
{
    __shared__ float4 s_c4[64];   // (p, q, r, beta)
    __shared__ float  s_cg[64];   // gamma
    __shared__ float4 s_we[64];   // omega rows [0:64), rank 4
    __shared__ float4 s_wo[64];   // omega rows [64:128), rank 4

    const int tid = threadIdx.x;
    const int b   = blockIdx.y;

    if (tid < 64) {
        float al = alpha[tid], m = mu[tid];
        float a2 = al * al * L2E;
        s_c4[tid] = make_float4(-a2, 2.f * a2 * m, -a2 * m * m, beta[tid]);
        s_cg[tid] = gamma[tid];
    }
    // omega[b] = b3 + sum of 8 deterministic split-K partials
    for (int j = tid; j < 512; j += 256) {
        float v = b3[j];
        #pragma unroll
        for (int p = 0; p < 8; p++)
            v += g_P3[(size_t)p * 64 * 512 + (size_t)b * 512 + j];
        if (j < 256) ((float*)s_we)[j] = v;
        else         ((float*)s_wo)[j - 256] = v;
    }
    __syncthreads();

    const float* tb = t + (size_t)b * 4096;
    const int s0 = blockIdx.x * 512 + tid;
    const int s1 = s0 + 256;
    const float t0 = tb[s0], t1 = tb[s1];
    const float t0q = t0 * t0, t1q = t1 * t1;

    float4 ae0 = make_float4(0.f, 0.f, 0.f, 0.f);
    float4 ao0 = ae0, ae1 = ae0, ao1 = ae0;

    #pragma unroll 8
    for (int nb = 0; nb < 64; nb++) {
        float4 c = s_c4[nb];
        float  g = s_cg[nb];

        float a0 = fmaf(c.x, t0q, fmaf(c.y, t0, c.z));
        float a1 = fmaf(c.x, t1q, fmaf(c.y, t1, c.z));
        float e0, e1;
        asm("ex2.approx.f32 %0, %1;" : "=f"(e0) : "f"(a0));
        asm("ex2.approx.f32 %0, %1;" : "=f"(e1) : "f"(a1));
        float h0 = e0 * __cosf(fmaf(c.w, t0, g));
        float h1 = e1 * __cosf(fmaf(c.w, t1, g));

        float4 we = s_we[nb], wo = s_wo[nb];
        ae0.x = fmaf(h0, we.x, ae0.x); ae0.y = fmaf(h0, we.y, ae0.y);
        ae0.z = fmaf(h0, we.z, ae0.z); ae0.w = fmaf(h0, we.w, ae0.w);
        ao0.x = fmaf(h0, wo.x, ao0.x); ao0.y = fmaf(h0, wo.y, ao0.y);
        ao0.z = fmaf(h0, wo.z, ao0.z); ao0.w = fmaf(h0, wo.w, ao0.w);
        ae1.x = fmaf(h1, we.x, ae1.x); ae1.y = fmaf(h1, we.y, ae1.y);
        ae1.z = fmaf(h1, we.z, ae1.z); ae1.w = fmaf(h1, we.w, ae1.w);
        ao1.x = fmaf(h1, wo.x, ao1.x); ao1.y = fmaf(h1, wo.y, ao1.y);
        ao1.z = fmaf(h1, wo.z, ao1.z); ao1.w = fmaf(h1, wo.w, ao1.w);
    }

    // Interleaved output: row 2s (even) then row 2s+1 (odd), rank-4 each =
    // 8 consecutive floats at b*32768 + 8*s.
    float* ob = out + (size_t)b * 32768;
    float4* o0 = reinterpret_cast<float4*>(ob + 8 * (size_t)s0);
    o0[0] = ae0; o0[1] = ao0;
    float4* o1 = reinterpret_cast<float4*>(ob + 8 * (size_t)s1);
    o1[0] = ae1; o1[1] = ao1;
}

extern "C" void kernel_launch(void* const* d_in, const int* in_sizes, int n_in,
                              void* d_out, int out_size) {
    const float* f     = (const float*)d_in[0];
    const float* t     = (const float*)d_in[1];
    const float* W1    = (const float*)d_in[2];
    const float* b1    = (const float*)d_in[3];
    const float* W2    = (const float*)d_in[4];
    const float* b2    = (const float*)d_in[5];
    const float* W3    = (const float*)d_in[6];
    const float* b3    = (const float*)d_in[7];
    const float* mu    = (const float*)d_in[8];
    const float* alpha = (const float*)d_in[9];
    const float* beta  = (const float*)d_in[10];
    const float* gamma = (const float*)d_in[11];
    float* out = (float*)d_out;

    void *h1p, *p2p, *p3p;
    cudaGetSymbolAddress(&h1p, g_h1);
    cudaGetSymbolAddress(&p2p, g_P2);
    cudaGetSymbolAddress(&p3p, g_P3);
    float* h1 = (float*)h1p;
    float* P2 = (float*)p2p;
    float* P3 = (float*)p3p;

    // Layer 1: h1 = relu(f @ W1 + b1)   [64x512], K=128, 32 blocks
    gemm_part<<<dim3(32, 1), 256>>>(f, nullptr, 0, nullptr, 128,
                                    W1, 512, b1, 1, h1);
    // Layer 2: P2[s] = h1 @ W2 (K-split 4)   [64x1024], 256 blocks
    gemm_part<<<dim3(64, 4), 256>>>(h1, nullptr, 0, nullptr, 512,
                                    W2, 1024, nullptr, 0, P2);
    // Layer 3: P3[s] = relu(b2 + sum P2) @ W3 (K-split 8)  [64x512], 256 blocks
    gemm_part<<<dim3(32, 8), 256>>>(nullptr, P2, 4, b2, 1024,
                                    W3, 512, nullptr, 0, P3);
    // Fused basis + einsum + interleave
    subspace_main<<<dim3(8, 64), 256>>>(t, mu, alpha, beta, gamma, b3, out);
}

// round 3
// speedup vs baseline: 1.1848x; 1.1848x over previous
#include <cuda_runtime.h>
#include <cstdint>

#define L2E 1.4426950408889634f
typedef unsigned long long ull;

// Scratch (static device globals — no runtime allocation)
__device__ float g_P1[2 * 64 * 512];    // split-K partials of f@W1
__device__ float g_P2[4 * 64 * 1024];   // split-K partials of relu(h1)@W2
__device__ float g_P3[8 * 64 * 512];    // split-K partials of relu(h2)@W3

// ---- packed f32x2 helpers (Blackwell FFMA2) --------------------------------
__device__ __forceinline__ ull pk2(float lo, float hi) {
    ull r; asm("mov.b64 %0, {%1, %2};" : "=l"(r) : "f"(lo), "f"(hi)); return r;
}
__device__ __forceinline__ void upk2(float& lo, float& hi, ull v) {
    asm("mov.b64 {%0, %1}, %2;" : "=f"(lo), "=f"(hi) : "l"(v));
}
__device__ __forceinline__ ull fma2(ull a, ull b, ull c) {
    ull d; asm("fma.rn.f32x2 %0, %1, %2, %3;" : "=l"(d) : "l"(a), "l"(b), "l"(c)); return d;
}
__device__ __forceinline__ ull mul2(ull a, ull b) {
    ull d; asm("mul.rn.f32x2 %0, %1, %2;" : "=l"(d) : "l"(a), "l"(b)); return d;
}

// ---------------------------------------------------------------------------
// Split-K GEMM partial (M=64): out[y][m][n0+n] = sum_{k in slice} Aval(m,k)*W[k][n]
// Aval = A[m][k] (raw) or relu(abias[k] + sum_p Aparts[p][m][k]).
// A tile staged fully to shared once; W double-buffered in 32-k chunks.
// Block: 256 thr, 64x32 output tile, 8 outputs/thread.
// ---------------------------------------------------------------------------
template <int KS>
__global__ __launch_bounds__(256) void gemm_part(
    const float* __restrict__ A,
    const float* __restrict__ Aparts, int nparts,
    const float* __restrict__ abias,
    int K_full,
    const float* __restrict__ W, int N,
    float* __restrict__ out)
{
    __shared__ float As[64 * KS];
    __shared__ float Ws[2][32][32];

    const int tid = threadIdx.x;
    const int n0  = blockIdx.x * 32;
    const int k0  = blockIdx.y * KS;
    out += (size_t)blockIdx.y * 64 * N;

    // Stage A tile [64 x KS] (float4, coalesced within rows)
    constexpr int KQ4 = KS / 4;
    #pragma unroll
    for (int f = tid; f < 64 * KQ4; f += 256) {
        int m = f / KQ4, kq = f - m * KQ4;
        int k = k0 + 4 * kq;
        float4 v;
        if (A) {
            v = *(const float4*)(A + (size_t)m * K_full + k);
        } else {
            v = *(const float4*)(abias + k);
            for (int p = 0; p < nparts; p++) {
                float4 w = *(const float4*)(Aparts + (size_t)p * 64 * K_full
                                            + (size_t)m * K_full + k);
                v.x += w.x; v.y += w.y; v.z += w.z; v.w += w.w;
            }
            v.x = fmaxf(v.x, 0.f); v.y = fmaxf(v.y, 0.f);
            v.z = fmaxf(v.z, 0.f); v.w = fmaxf(v.w, 0.f);
        }
        *(float4*)&As[m * KS + 4 * kq] = v;
    }

    const int iw = tid >> 3, nn = (tid & 7) * 4;
    // Prefetch W chunk 0
    {
        float4 w = *(const float4*)(W + (size_t)(k0 + iw) * N + n0 + nn);
        *(float4*)&Ws[0][iw][nn] = w;
    }
    __syncthreads();

    const int n  = tid & 31;
    const int mb = (tid >> 5) * 8;
    float acc[8] = {0,0,0,0,0,0,0,0};

    constexpr int NC = KS / 32;
    #pragma unroll
    for (int c = 0; c < NC; c++) {
        if (c + 1 < NC) {
            float4 w = *(const float4*)(W + (size_t)(k0 + (c+1)*32 + iw) * N + n0 + nn);
            *(float4*)&Ws[(c + 1) & 1][iw][nn] = w;
        }
        const float* wsb = &Ws[c & 1][0][0];
        const int kc = c * 32;
        #pragma unroll
        for (int k = 0; k < 32; k += 4) {
            float w0 = wsb[(k+0)*32 + n], w1 = wsb[(k+1)*32 + n];
            float w2 = wsb[(k+2)*32 + n], w3 = wsb[(k+3)*32 + n];
            #pragma unroll
            for (int q = 0; q < 8; q++) {
                float4 av = *(const float4*)&As[(mb + q) * KS + kc + k];
                float a = acc[q];
                a = fmaf(av.x, w0, a); a = fmaf(av.y, w1, a);
                a = fmaf(av.z, w2, a); a = fmaf(av.w, w3, a);
                acc[q] = a;
            }
        }
        __syncthreads();
    }

    #pragma unroll
    for (int q = 0; q < 8; q++)
        out[(size_t)(mb + q) * N + n0 + n] = acc[q];
}

// ---------------------------------------------------------------------------
// Fused basis + rank-4 einsum + interleave, f32x2-packed across the 2 elements
// each thread owns. Coefficients & omega pre-duplicated in shared (uniform LDS).
// ---------------------------------------------------------------------------
__global__ __launch_bounds__(256) void subspace_main(
    const float* __restrict__ t,
    const float* __restrict__ mu, const float* __restrict__ alpha,
    const float* __restrict__ beta, const float* __restrict__ gamma,
    const float* __restrict__ b3,
    float* __restrict__ out)
{
    __shared__ float2 s_pp[64], s_qq[64], s_rr[64], s_bb[64], s_gg[64];
    __shared__ ull    s_w[64][8];   // duplicated omega: [nb][0:4 even ranks, 4:8 odd]

    const int tid = threadIdx.x;
    const int b   = blockIdx.y;

    if (tid < 64) {
        float al = alpha[tid], m = mu[tid];
        float a2 = al * al * L2E;
        float p = -a2, q = 2.f * a2 * m, r = -a2 * m * m;
        s_pp[tid] = make_float2(p, p);
        s_qq[tid] = make_float2(q, q);
        s_rr[tid] = make_float2(r, r);
        float be = beta[tid], ga = gamma[tid];
        s_bb[tid] = make_float2(be, be);
        s_gg[tid] = make_float2(ga, ga);
    }
    for (int j = tid; j < 512; j += 256) {
        float v = b3[j];
        #pragma unroll
        for (int p = 0; p < 8; p++)
            v += g_P3[(size_t)p * 64 * 512 + (size_t)b * 512 + j];
        int row = j >> 2, r = j & 3;
        int nb = row & 63;
        int pi = (row < 64) ? r : (4 + r);
        s_w[nb][pi] = pk2(v, v);
    }
    __syncthreads();

    const float* tb = t + (size_t)b * 4096;
    const int s0 = blockIdx.x * 512 + tid;
    const int s1 = s0 + 256;
    const float t0 = tb[s0], t1 = tb[s1];
    const ull tt = pk2(t0, t1);
    const ull tq = pk2(t0 * t0, t1 * t1);

    ull acc[8] = {0,0,0,0,0,0,0,0};   // bit pattern of (0.f, 0.f)

    #pragma unroll 4
    for (int nb = 0; nb < 64; nb++) {
        ull pp = *(const ull*)&s_pp[nb];
        ull qq = *(const ull*)&s_qq[nb];
        ull rr = *(const ull*)&s_rr[nb];
        ull a  = fma2(pp, tq, fma2(qq, tt, rr));
        float a0, a1; upk2(a0, a1, a);
        float e0, e1;
        asm("ex2.approx.f32 %0, %1;" : "=f"(e0) : "f"(a0));
        asm("ex2.approx.f32 %0, %1;" : "=f"(e1) : "f"(a1));

        ull bb = *(const ull*)&s_bb[nb];
        ull gg = *(const ull*)&s_gg[nb];
        ull ca = fma2(bb, tt, gg);
        float c0, c1; upk2(c0, c1, ca);
        ull h = mul2(pk2(e0, e1), pk2(__cosf(c0), __cosf(c1)));

        #pragma unroll
        for (int j = 0; j < 8; j++)
            acc[j] = fma2(h, s_w[nb][j], acc[j]);
    }

    float lo[8], hi[8];
    #pragma unroll
    for (int j = 0; j < 8; j++) upk2(lo[j], hi[j], acc[j]);

    float* ob = out + (size_t)b * 32768;
    float4* o0 = reinterpret_cast<float4*>(ob + 8 * (size_t)s0);
    o0[0] = make_float4(lo[0], lo[1], lo[2], lo[3]);
    o0[1] = make_float4(lo[4], lo[5], lo[6], lo[7]);
    float4* o1 = reinterpret_cast<float4*>(ob + 8 * (size_t)s1);
    o1[0] = make_float4(hi[0], hi[1], hi[2], hi[3]);
    o1[1] = make_float4(hi[4], hi[5], hi[6], hi[7]);
}

extern "C" void kernel_launch(void* const* d_in, const int* in_sizes, int n_in,
                              void* d_out, int out_size) {
    const float* f     = (const float*)d_in[0];
    const float* t     = (const float*)d_in[1];
    const float* W1    = (const float*)d_in[2];
    const float* b1    = (const float*)d_in[3];
    const float* W2    = (const float*)d_in[4];
    const float* b2    = (const float*)d_in[5];
    const float* W3    = (const float*)d_in[6];
    const float* b3    = (const float*)d_in[7];
    const float* mu    = (const float*)d_in[8];
    const float* alpha = (const float*)d_in[9];
    const float* beta  = (const float*)d_in[10];
    const float* gamma = (const float*)d_in[11];
    float* out = (float*)d_out;

    void *p1p, *p2p, *p3p;
    cudaGetSymbolAddress(&p1p, g_P1);
    cudaGetSymbolAddress(&p2p, g_P2);
    cudaGetSymbolAddress(&p3p, g_P3);
    float* P1 = (float*)p1p;
    float* P2 = (float*)p2p;
    float* P3 = (float*)p3p;

    // L1: P1[2] = f @ W1 (K=128, Kslice=64), 32 blocks
    gemm_part<64><<<dim3(16, 2), 256>>>(f, nullptr, 0, nullptr, 128,
                                        W1, 512, P1);
    // L2: P2[4] = relu(b1 + sum P1) @ W2 (K=512, Kslice=128), 128 blocks
    gemm_part<128><<<dim3(32, 4), 256>>>(nullptr, P1, 2, b1, 512,
                                         W2, 1024, P2);
    // L3: P3[8] = relu(b2 + sum P2) @ W3 (K=1024, Kslice=128), 128 blocks
    gemm_part<128><<<dim3(16, 8), 256>>>(nullptr, P2, 4, b2, 1024,
                                         W3, 512, P3);
    // Fused basis + einsum + interleave (omega = b3 + sum P3)
    subspace_main<<<dim3(8, 64), 256>>>(t, mu, alpha, beta, gamma, b3, out);
}

// round 4
// speedup vs baseline: 1.1875x; 1.0022x over previous
#include <cuda_runtime.h>
#include <cstdint>

#define L2E 1.4426950408889634f
typedef unsigned long long ull;

// Scratch (static device globals — no runtime allocation)
__device__ float g_P1[2 * 64 * 512];    // split-K partials of f@W1
__device__ float g_P2[4 * 64 * 1024];   // split-K partials of relu(h1)@W2
__device__ float g_P3[8 * 64 * 512];    // split-K partials of relu(h2)@W3

// ---- packed f32x2 helpers (Blackwell FFMA2) --------------------------------
__device__ __forceinline__ ull pk2(float lo, float hi) {
    ull r; asm("mov.b64 %0, {%1, %2};" : "=l"(r) : "f"(lo), "f"(hi)); return r;
}
__device__ __forceinline__ void upk2(float& lo, float& hi, ull v) {
    asm("mov.b64 {%0, %1}, %2;" : "=f"(lo), "=f"(hi) : "l"(v));
}
__device__ __forceinline__ ull fma2(ull a, ull b, ull c) {
    ull d; asm("fma.rn.f32x2 %0, %1, %2, %3;" : "=l"(d) : "l"(a), "l"(b), "l"(c)); return d;
}
__device__ __forceinline__ ull mul2(ull a, ull b) {
    ull d; asm("mul.rn.f32x2 %0, %1, %2;" : "=l"(d) : "l"(a), "l"(b)); return d;
}

// ---------------------------------------------------------------------------
// Split-K GEMM partial (M=64): out[y][m][n0+n] = sum_{k in slice} Aval(m,k)*W[k][n]
// Aval = A[m][k] (raw) or relu(abias[k] + sum_p Aparts[p][m][k]).
// A staged to shared once; W double-buffered in 32-k chunks.
// Inner loop uses fma.rn.f32x2 (2 k-steps per instr); lo+hi added at epilogue.
// ---------------------------------------------------------------------------
template <int KS>
__global__ __launch_bounds__(256) void gemm_part(
    const float* __restrict__ A,
    const float* __restrict__ Aparts, int nparts,
    const float* __restrict__ abias,
    int K_full,
    const float* __restrict__ W, int N,
    float* __restrict__ out)
{
    __shared__ float As[64 * KS];
    __shared__ float Ws[2][32][32];

    const int tid = threadIdx.x;
    const int n0  = blockIdx.x * 32;
    const int k0  = blockIdx.y * KS;
    out += (size_t)blockIdx.y * 64 * N;

    // Stage A tile [64 x KS] (float4, coalesced within rows)
    constexpr int KQ4 = KS / 4;
    #pragma unroll
    for (int f = tid; f < 64 * KQ4; f += 256) {
        int m = f / KQ4, kq = f - m * KQ4;
        int k = k0 + 4 * kq;
        float4 v;
        if (A) {
            v = *(const float4*)(A + (size_t)m * K_full + k);
        } else {
            v = *(const float4*)(abias + k);
            for (int p = 0; p < nparts; p++) {
                float4 w = *(const float4*)(Aparts + (size_t)p * 64 * K_full
                                            + (size_t)m * K_full + k);
                v.x += w.x; v.y += w.y; v.z += w.z; v.w += w.w;
            }
            v.x = fmaxf(v.x, 0.f); v.y = fmaxf(v.y, 0.f);
            v.z = fmaxf(v.z, 0.f); v.w = fmaxf(v.w, 0.f);
        }
        *(float4*)&As[m * KS + 4 * kq] = v;
    }

    const int iw = tid >> 3, nn = (tid & 7) * 4;
    // Prefetch W chunk 0
    {
        float4 w = *(const float4*)(W + (size_t)(k0 + iw) * N + n0 + nn);
        *(float4*)&Ws[0][iw][nn] = w;
    }
    __syncthreads();

    const int n  = tid & 31;
    const int mb = (tid >> 5) * 8;
    ull acc2[8] = {0,0,0,0,0,0,0,0};   // packed (even-k, odd-k) partial sums

    constexpr int NC = KS / 32;
    #pragma unroll
    for (int c = 0; c < NC; c++) {
        if (c + 1 < NC) {
            float4 w = *(const float4*)(W + (size_t)(k0 + (c+1)*32 + iw) * N + n0 + nn);
            *(float4*)&Ws[(c + 1) & 1][iw][nn] = w;
        }
        const float* wsb = &Ws[c & 1][0][0];
        const int kc = c * 32;
        #pragma unroll
        for (int k = 0; k < 32; k += 4) {
            float w0 = wsb[(k+0)*32 + n], w1 = wsb[(k+1)*32 + n];
            float w2 = wsb[(k+2)*32 + n], w3 = wsb[(k+3)*32 + n];
            ull wA = pk2(w0, w1), wB = pk2(w2, w3);
            #pragma unroll
            for (int q = 0; q < 8; q++) {
                ulonglong2 av = *(const ulonglong2*)&As[(mb + q) * KS + kc + k];
                acc2[q] = fma2(av.x, wA, acc2[q]);
                acc2[q] = fma2(av.y, wB, acc2[q]);
            }
        }
        __syncthreads();
    }

    #pragma unroll
    for (int q = 0; q < 8; q++) {
        float lo, hi; upk2(lo, hi, acc2[q]);
        out[(size_t)(mb + q) * N + n0 + n] = lo + hi;
    }
}

// ---------------------------------------------------------------------------
// Fused basis + rank-4 einsum + interleave.
// 128 threads, 4 s-elements/thread (2 f32x2 pairs) -> broadcast LDS amortized.
// All coefficients/omega stored PRE-DUPLICATED so LDS.128 lands directly in
// f32x2 register pairs (no packing MOVs).
// ---------------------------------------------------------------------------
__global__ __launch_bounds__(128) void subspace_main(
    const float* __restrict__ t,
    const float* __restrict__ mu, const float* __restrict__ alpha,
    const float* __restrict__ beta, const float* __restrict__ gamma,
    const float* __restrict__ b3,
    float* __restrict__ out)
{
    __shared__ float4 s_c1[64];      // (p,p,q,q)
    __shared__ float4 s_c2[64];      // (r,r,beta,beta)
    __shared__ float2 s_c3[64];      // (gamma,gamma)
    __shared__ float  s_we[64][8];   // (w0,w0,w1,w1,w2,w2,w3,w3) even rows
    __shared__ float  s_wo[64][8];   // odd rows

    const int tid = threadIdx.x;
    const int b   = blockIdx.y;

    if (tid < 64) {
        float al = alpha[tid], m = mu[tid];
        float a2 = al * al * L2E;
        float p = -a2, q = 2.f * a2 * m, r = -a2 * m * m;
        s_c1[tid] = make_float4(p, p, q, q);
        s_c2[tid] = make_float4(r, r, beta[tid], beta[tid]);
        float ga = gamma[tid];
        s_c3[tid] = make_float2(ga, ga);
    }
    for (int j = tid; j < 512; j += 128) {
        float v = b3[j];
        #pragma unroll
        for (int p = 0; p < 8; p++)
            v += g_P3[(size_t)p * 64 * 512 + (size_t)b * 512 + j];
        int row = j >> 2, r = j & 3;
        int nb = row & 63;
        float* dst = (row < 64) ? s_we[nb] : s_wo[nb];
        dst[2 * r] = v; dst[2 * r + 1] = v;
    }
    __syncthreads();

    const float* tb = t + (size_t)b * 4096;
    const int s0 = blockIdx.x * 512 + tid;
    const float ta = tb[s0],       tbv = tb[s0 + 128];
    const float tc = tb[s0 + 256], td  = tb[s0 + 384];
    const ull tt0 = pk2(ta, tbv), tt1 = pk2(tc, td);
    const ull tq0 = pk2(ta * ta, tbv * tbv), tq1 = pk2(tc * tc, td * td);

    ull acc[16];   // [pair][j: 0..3 even ranks, 4..7 odd ranks]
    #pragma unroll
    for (int j = 0; j < 16; j++) acc[j] = 0ull;

    #pragma unroll 4
    for (int nb = 0; nb < 64; nb++) {
        ulonglong2 c1 = *(const ulonglong2*)&s_c1[nb];  // (p,p) (q,q)
        ulonglong2 c2 = *(const ulonglong2*)&s_c2[nb];  // (r,r) (b,b)
        ull gg = *(const ull*)&s_c3[nb];                // (g,g)
        ulonglong2 we01 = *(const ulonglong2*)&s_we[nb][0];
        ulonglong2 we23 = *(const ulonglong2*)&s_we[nb][4];
        ulonglong2 wo01 = *(const ulonglong2*)&s_wo[nb][0];
        ulonglong2 wo23 = *(const ulonglong2*)&s_wo[nb][4];

        #pragma unroll
        for (int P = 0; P < 2; P++) {
            const ull tt = P ? tt1 : tt0;
            const ull tq = P ? tq1 : tq0;

            ull a = fma2(c1.x, tq, fma2(c1.y, tt, c2.x));
            float a0, a1; upk2(a0, a1, a);
            float e0, e1;
            asm("ex2.approx.f32 %0, %1;" : "=f"(e0) : "f"(a0));
            asm("ex2.approx.f32 %0, %1;" : "=f"(e1) : "f"(a1));

            ull ca = fma2(c2.y, tt, gg);
            float c0, c1f; upk2(c0, c1f, ca);
            ull h = mul2(pk2(e0, e1), pk2(__cosf(c0), __cosf(c1f)));

            ull* ac = acc + P * 8;
            ac[0] = fma2(h, we01.x, ac[0]);
            ac[1] = fma2(h, we01.y, ac[1]);
            ac[2] = fma2(h, we23.x, ac[2]);
            ac[3] = fma2(h, we23.y, ac[3]);
            ac[4] = fma2(h, wo01.x, ac[4]);
            ac[5] = fma2(h, wo01.y, ac[5]);
            ac[6] = fma2(h, wo23.x, ac[6]);
            ac[7] = fma2(h, wo23.y, ac[7]);
        }
    }

    float* ob = out + (size_t)b * 32768;
    #pragma unroll
    for (int P = 0; P < 2; P++) {
        float lo[8], hi[8];
        #pragma unroll
        for (int j = 0; j < 8; j++) upk2(lo[j], hi[j], acc[P * 8 + j]);
        const int sA = s0 + P * 256;        // lo element
        const int sB = sA + 128;            // hi element
        float4* oA = reinterpret_cast<float4*>(ob + 8 * (size_t)sA);
        oA[0] = make_float4(lo[0], lo[1], lo[2], lo[3]);
        oA[1] = make_float4(lo[4], lo[5], lo[6], lo[7]);
        float4* oB = reinterpret_cast<float4*>(ob + 8 * (size_t)sB);
        oB[0] = make_float4(hi[0], hi[1], hi[2], hi[3]);
        oB[1] = make_float4(hi[4], hi[5], hi[6], hi[7]);
    }
}

extern "C" void kernel_launch(void* const* d_in, const int* in_sizes, int n_in,
                              void* d_out, int out_size) {
    const float* f     = (const float*)d_in[0];
    const float* t     = (const float*)d_in[1];
    const float* W1    = (const float*)d_in[2];
    const float* b1    = (const float*)d_in[3];
    const float* W2    = (const float*)d_in[4];
    const float* b2    = (const float*)d_in[5];
    const float* W3    = (const float*)d_in[6];
    const float* b3    = (const float*)d_in[7];
    const float* mu    = (const float*)d_in[8];
    const float* alpha = (const float*)d_in[9];
    const float* beta  = (const float*)d_in[10];
    const float* gamma = (const float*)d_in[11];
    float* out = (float*)d_out;

    void *p1p, *p2p, *p3p;
    cudaGetSymbolAddress(&p1p, g_P1);
    cudaGetSymbolAddress(&p2p, g_P2);
    cudaGetSymbolAddress(&p3p, g_P3);
    float* P1 = (float*)p1p;
    float* P2 = (float*)p2p;
    float* P3 = (float*)p3p;

    // L1: P1[2] = f @ W1 (K=128, Kslice=64), 32 blocks
    gemm_part<64><<<dim3(16, 2), 256>>>(f, nullptr, 0, nullptr, 128,
                                        W1, 512, P1);
    // L2: P2[4] = relu(b1 + sum P1) @ W2 (K=512, Kslice=128), 128 blocks
    gemm_part<128><<<dim3(32, 4), 256>>>(nullptr, P1, 2, b1, 512,
                                         W2, 1024, P2);
    // L3: P3[8] = relu(b2 + sum P2) @ W3 (K=1024, Kslice=128), 128 blocks
    gemm_part<128><<<dim3(16, 8), 256>>>(nullptr, P2, 4, b2, 1024,
                                         W3, 512, P3);
    // Fused basis + einsum + interleave (omega = b3 + sum P3)
    subspace_main<<<dim3(8, 64), 128>>>(t, mu, alpha, beta, gamma, b3, out);
}

// round 7
// speedup vs baseline: 1.1927x; 1.0044x over previous
#include <cuda_runtime.h>
#include <cstdint>

#define L2E 1.4426950408889634f
typedef unsigned long long ull;

// Scratch (static device globals — no runtime allocation)
__device__ float g_P1[2 * 64 * 512];    // split-K partials of f@W1
__device__ float g_P2[4 * 64 * 1024];   // split-K partials of relu(h1)@W2
__device__ float g_P3[8 * 64 * 512];    // split-K partials of relu(h2)@W3

// Global-barrier state (returns to all-zero at end of every launch)
__device__ unsigned g_cnt[2] = {0, 0};
__device__ unsigned g_exit[2] = {0, 0};

// ---- packed f32x2 helpers ---------------------------------------------------
__device__ __forceinline__ ull pk2(float lo, float hi) {
    ull r; asm("mov.b64 %0, {%1, %2};" : "=l"(r) : "f"(lo), "f"(hi)); return r;
}
__device__ __forceinline__ void upk2(float& lo, float& hi, ull v) {
    asm("mov.b64 {%0, %1}, %2;" : "=f"(lo), "=f"(hi) : "l"(v));
}
__device__ __forceinline__ ull fma2(ull a, ull b, ull c) {
    ull d; asm("fma.rn.f32x2 %0, %1, %2, %3;" : "=l"(d) : "l"(a), "l"(b), "l"(c)); return d;
}
__device__ __forceinline__ ull mul2(ull a, ull b) {
    ull d; asm("mul.rn.f32x2 %0, %1, %2;" : "=l"(d) : "l"(a), "l"(b)); return d;
}

// ---- software grid barrier (all blocks resident: grid <= 148) ---------------
__device__ __forceinline__ void grid_bar(int i, unsigned nblk) {
    __syncthreads();
    if (threadIdx.x == 0) {
        __threadfence();
        atomicAdd(&g_cnt[i], 1u);
        while (*(volatile unsigned*)&g_cnt[i] < nblk) __nanosleep(40);
        __threadfence();
        unsigned e = atomicAdd(&g_exit[i], 1u);
        if (e == nblk - 1) {            // last exiter: everyone has left the spin
            g_cnt[i] = 0; __threadfence(); g_exit[i] = 0;
        }
    }
    __syncthreads();
}

// ---------------------------------------------------------------------------
// GEMM tile body (same math/layout as the passing R4 kernel, KS runtime).
// out[m][n0+n] = over k-slice [k0, k0+KS): Aval(m,k)*W[k][n]
// Aval = A[m][k] (raw) or relu(abias[k] + sum_p Aparts[p][m][k]).
// ---------------------------------------------------------------------------
__device__ void gemm_tile(
    float* As, float (*Ws)[32][32],
    const float* __restrict__ A,
    const float* __restrict__ Aparts, int nparts,
    const float* __restrict__ abias,
    int K_full, int KS,
    const float* __restrict__ W, int N,
    int n0, int k0,
    float* __restrict__ out)
{
    const int tid = threadIdx.x;

    // Stage A tile [64 x KS]
    const int KQ4 = KS / 4;
    for (int f = tid; f < 64 * KQ4; f += 256) {
        int m = f / KQ4, kq = f - m * KQ4;
        int k = k0 + 4 * kq;
        float4 v;
        if (A) {
            v = *(const float4*)(A + (size_t)m * K_full + k);
        } else {
            v = *(const float4*)(abias + k);
            for (int p = 0; p < nparts; p++) {
                float4 w = *(const float4*)(Aparts + (size_t)p * 64 * K_full
                                            + (size_t)m * K_full + k);
                v.x += w.x; v.y += w.y; v.z += w.z; v.w += w.w;
            }
            v.x = fmaxf(v.x, 0.f); v.y = fmaxf(v.y, 0.f);
            v.z = fmaxf(v.z, 0.f); v.w = fmaxf(v.w, 0.f);
        }
        *(float4*)&As[m * KS + 4 * kq] = v;
    }

    const int iw = tid >> 3, nn = (tid & 7) * 4;
    {
        float4 w = *(const float4*)(W + (size_t)(k0 + iw) * N + n0 + nn);
        *(float4*)&Ws[0][iw][nn] = w;
    }
    __syncthreads();

    const int n  = tid & 31;
    const int mb = (tid >> 5) * 8;
    ull acc2[8] = {0,0,0,0,0,0,0,0};

    const int NC = KS / 32;
    for (int c = 0; c < NC; c++) {
        if (c + 1 < NC) {
            float4 w = *(const float4*)(W + (size_t)(k0 + (c+1)*32 + iw) * N + n0 + nn);
            *(float4*)&Ws[(c + 1) & 1][iw][nn] = w;
        }
        const float* wsb = &Ws[c & 1][0][0];
        const int kc = c * 32;
        #pragma unroll
        for (int k = 0; k < 32; k += 4) {
            float w0 = wsb[(k+0)*32 + n], w1 = wsb[(k+1)*32 + n];
            float w2 = wsb[(k+2)*32 + n], w3 = wsb[(k+3)*32 + n];
            ull wA = pk2(w0, w1), wB = pk2(w2, w3);
            #pragma unroll
            for (int q = 0; q < 8; q++) {
                ulonglong2 av = *(const ulonglong2*)&As[(mb + q) * KS + kc + k];
                acc2[q] = fma2(av.x, wA, acc2[q]);
                acc2[q] = fma2(av.y, wB, acc2[q]);
            }
        }
        __syncthreads();
    }

    #pragma unroll
    for (int q = 0; q < 8; q++) {
        float lo, hi; upk2(lo, hi, acc2[q]);
        out[(size_t)(mb + q) * N + n0 + n] = lo + hi;
    }
}

// ---------------------------------------------------------------------------
// Persistent fused MLP: all 3 layers in one launch, global barriers between.
// Grid MUST be 128 blocks (co-residency requirement for the spin barriers).
// ---------------------------------------------------------------------------
__global__ __launch_bounds__(256) void mlp_fused(
    const float* __restrict__ f,
    const float* __restrict__ W1, const float* __restrict__ b1,
    const float* __restrict__ W2, const float* __restrict__ b2,
    const float* __restrict__ W3)
{
    __shared__ float As[64 * 128];
    __shared__ float Ws[2][32][32];

    const int bid = blockIdx.x;

    // Phase 1: P1[2] = f @ W1  (N=512, K=128, KS=64) — 32 units
    if (bid < 32) {
        int n0 = (bid & 15) * 32, ks = bid >> 4;
        gemm_tile(As, Ws, f, nullptr, 0, nullptr, 128, 64, W1, 512,
                  n0, ks * 64, g_P1 + (size_t)ks * 64 * 512);
    }
    grid_bar(0, 128);

    // Phase 2: P2[4] = relu(b1 + sum P1) @ W2  (N=1024, K=512, KS=128) — 128 units
    {
        int n0 = (bid & 31) * 32, ks = bid >> 5;
        gemm_tile(As, Ws, nullptr, g_P1, 2, b1, 512, 128, W2, 1024,
                  n0, ks * 128, g_P2 + (size_t)ks * 64 * 1024);
    }
    grid_bar(1, 128);

    // Phase 3: P3[8] = relu(b2 + sum P2) @ W3  (N=512, K=1024, KS=128) — 128 units
    {
        int n0 = (bid & 15) * 32, ks = bid >> 4;
        gemm_tile(As, Ws, nullptr, g_P2, 4, b2, 1024, 128, W3, 512,
                  n0, ks * 128, g_P3 + (size_t)ks * 64 * 512);
    }
}

// ---------------------------------------------------------------------------
// Fused basis + rank-4 einsum + interleave.
// 256 threads, 2 s-elements/thread (1 f32x2 pair), grid (8, 64) = 512 blocks
// -> ~28 warps/SM. Coeffs/omega pre-duplicated: LDS.128 -> f32x2 pairs direct.
// ---------------------------------------------------------------------------
__global__ __launch_bounds__(256) void subspace_main(
    const float* __restrict__ t,
    const float* __restrict__ mu, const float* __restrict__ alpha,
    const float* __restrict__ beta, const float* __restrict__ gamma,
    const float* __restrict__ b3,
    float* __restrict__ out)
{
    __shared__ float4 s_c1[64];      // (p,p,q,q)
    __shared__ float4 s_c2[64];      // (r,r,beta,beta)
    __shared__ float2 s_c3[64];      // (gamma,gamma)
    __shared__ float  s_we[64][8];   // duplicated even-row omega
    __shared__ float  s_wo[64][8];   // duplicated odd-row omega

    const int tid = threadIdx.x;
    const int b   = blockIdx.y;

    if (tid < 64) {
        float al = alpha[tid], m = mu[tid];
        float a2 = al * al * L2E;
        s_c1[tid] = make_float4(-a2, -a2, 2.f * a2 * m, 2.f * a2 * m);
        float r = -a2 * m * m, be = beta[tid];
        s_c2[tid] = make_float4(r, r, be, be);
        float ga = gamma[tid];
        s_c3[tid] = make_float2(ga, ga);
    }
    for (int j = tid; j < 512; j += 256) {
        float v = b3[j];
        #pragma unroll
        for (int p = 0; p < 8; p++)
            v += g_P3[(size_t)p * 64 * 512 + (size_t)b * 512 + j];
        int row = j >> 2, r = j & 3;
        int nb = row & 63;
        float* dst = (row < 64) ? s_we[nb] : s_wo[nb];
        dst[2 * r] = v; dst[2 * r + 1] = v;
    }
    __syncthreads();

    const float* tb = t + (size_t)b * 4096;
    const int s0 = blockIdx.x * 512 + tid;
    const float t0 = tb[s0], t1 = tb[s0 + 256];
    const ull tt = pk2(t0, t1);
    const ull tq = pk2(t0 * t0, t1 * t1);

    ull acc[8] = {0,0,0,0,0,0,0,0};

    #pragma unroll 4
    for (int nb = 0; nb < 64; nb++) {
        ulonglong2 c1 = *(const ulonglong2*)&s_c1[nb];  // (p,p)(q,q)
        ulonglong2 c2 = *(const ulonglong2*)&s_c2[nb];  // (r,r)(b,b)
        ull gg = *(const ull*)&s_c3[nb];                // (g,g)
        ulonglong2 we01 = *(const ulonglong2*)&s_we[nb][0];
        ulonglong2 we23 = *(const ulonglong2*)&s_we[nb][4];
        ulonglong2 wo01 = *(const ulonglong2*)&s_wo[nb][0];
        ulonglong2 wo23 = *(const ulonglong2*)&s_wo[nb][4];

        ull a = fma2(c1.x, tq, fma2(c1.y, tt, c2.x));
        float a0, a1; upk2(a0, a1, a);
        float e0, e1;
        asm("ex2.approx.f32 %0, %1;" : "=f"(e0) : "f"(a0));
        asm("ex2.approx.f32 %0, %1;" : "=f"(e1) : "f"(a1));

        ull ca = fma2(c2.y, tt, gg);
        float c0, c1f; upk2(c0, c1f, ca);
        ull h = mul2(pk2(e0, e1), pk2(__cosf(c0), __cosf(c1f)));

        acc[0] = fma2(h, we01.x, acc[0]);
        acc[1] = fma2(h, we01.y, acc[1]);
        acc[2] = fma2(h, we23.x, acc[2]);
        acc[3] = fma2(h, we23.y, acc[3]);
        acc[4] = fma2(h, wo01.x, acc[4]);
        acc[5] = fma2(h, wo01.y, acc[5]);
        acc[6] = fma2(h, wo23.x, acc[6]);
        acc[7] = fma2(h, wo23.y, acc[7]);
    }

    float lo[8], hi[8];
    #pragma unroll
    for (int j = 0; j < 8; j++) upk2(lo[j], hi[j], acc[j]);

    float* ob = out + (size_t)b * 32768;
    float4* o0 = reinterpret_cast<float4*>(ob + 8 * (size_t)s0);
    o0[0] = make_float4(lo[0], lo[1], lo[2], lo[3]);
    o0[1] = make_float4(lo[4], lo[5], lo[6], lo[7]);
    float4* o1 = reinterpret_cast<float4*>(ob + 8 * (size_t)(s0 + 256));
    o1[0] = make_float4(hi[0], hi[1], hi[2], hi[3]);
    o1[1] = make_float4(hi[4], hi[5], hi[6], hi[7]);
}

extern "C" void kernel_launch(void* const* d_in, const int* in_sizes, int n_in,
                              void* d_out, int out_size) {
    const float* f     = (const float*)d_in[0];
    const float* t     = (const float*)d_in[1];
    const float* W1    = (const float*)d_in[2];
    const float* b1    = (const float*)d_in[3];
    const float* W2    = (const float*)d_in[4];
    const float* b2    = (const float*)d_in[5];
    const float* W3    = (const float*)d_in[6];
    const float* b3    = (const float*)d_in[7];
    const float* mu    = (const float*)d_in[8];
    const float* alpha = (const float*)d_in[9];
    const float* beta  = (const float*)d_in[10];
    const float* gamma = (const float*)d_in[11];
    float* out = (float*)d_out;

    // Fused 3-layer MLP in one persistent launch (128 blocks, all co-resident)
    mlp_fused<<<128, 256>>>(f, W1, b1, W2, b2, W3);
    // Fused basis + einsum + interleave (omega = b3 + sum of 8 P3 partials)
    subspace_main<<<dim3(8, 64), 256>>>(t, mu, alpha, beta, gamma, b3, out);
}

// round 8
// speedup vs baseline: 1.2570x; 1.0539x over previous
#include <cuda_runtime.h>
#include <cstdint>

#define L2E 1.4426950408889634f
typedef unsigned long long ull;

// Scratch (static device globals — no runtime allocation)
__device__ float g_P1[4 * 64 * 512];     // split-K partials of f@W1
__device__ float g_P2[8 * 64 * 1024];    // split-K partials of relu(h1)@W2
__device__ float g_P3[16 * 64 * 512];    // split-K partials of relu(h2)@W3

// Grid-barrier state (returns to all-zero at end of every launch)
__device__ unsigned g_cnt[3]  = {0, 0, 0};
__device__ unsigned g_exit[3] = {0, 0, 0};

// ---- packed f32x2 helpers ---------------------------------------------------
__device__ __forceinline__ ull pk2(float lo, float hi) {
    ull r; asm("mov.b64 %0, {%1, %2};" : "=l"(r) : "f"(lo), "f"(hi)); return r;
}
__device__ __forceinline__ void upk2(float& lo, float& hi, ull v) {
    asm("mov.b64 {%0, %1}, %2;" : "=f"(lo), "=f"(hi) : "l"(v));
}
__device__ __forceinline__ ull fma2(ull a, ull b, ull c) {
    ull d; asm("fma.rn.f32x2 %0, %1, %2, %3;" : "=l"(d) : "l"(a), "l"(b), "l"(c)); return d;
}

// ---- software grid barrier: 512 blocks, co-residency guaranteed by
// __launch_bounds__(256,4) (148 SMs x 4 blocks = 592 >= 512) -----------------
__device__ __forceinline__ void grid_bar(int i) {
    __syncthreads();
    if (threadIdx.x == 0) {
        __threadfence();
        atomicAdd(&g_cnt[i], 1u);
        while (*(volatile unsigned*)&g_cnt[i] < 512u) __nanosleep(40);
        __threadfence();
        unsigned e = atomicAdd(&g_exit[i], 1u);
        if (e == 511u) {                 // last exiter: everyone left the spin
            g_cnt[i] = 0; __threadfence(); g_exit[i] = 0;
        }
    }
    __syncthreads();
}

// ---------------------------------------------------------------------------
// GEMM tile body (KS <= 64): out[m][n0+n] = sum_{k in [k0,k0+KS)} Aval(m,k)*W[k][n]
// Aval = A[m][k] (raw) or relu(abias[k] + sum_p Aparts[p][m][k]).
// A staged once to shared; W double-buffered in 32-k chunks; f32x2 inner loop.
// ---------------------------------------------------------------------------
__device__ void gemm_tile(
    float* As, float (*Ws)[32][32],
    const float* __restrict__ A,
    const float* __restrict__ Aparts, int nparts,
    const float* __restrict__ abias,
    int K_full, int KS,
    const float* __restrict__ W, int N,
    int n0, int k0,
    float* __restrict__ out)
{
    const int tid = threadIdx.x;

    // Stage A tile [64 x KS]
    const int KQ4 = KS / 4;
    for (int f = tid; f < 64 * KQ4; f += 256) {
        int m = f / KQ4, kq = f - m * KQ4;
        int k = k0 + 4 * kq;
        float4 v;
        if (A) {
            v = *(const float4*)(A + (size_t)m * K_full + k);
        } else {
            v = *(const float4*)(abias + k);
            for (int p = 0; p < nparts; p++) {
                float4 w = *(const float4*)(Aparts + (size_t)p * 64 * K_full
                                            + (size_t)m * K_full + k);
                v.x += w.x; v.y += w.y; v.z += w.z; v.w += w.w;
            }
            v.x = fmaxf(v.x, 0.f); v.y = fmaxf(v.y, 0.f);
            v.z = fmaxf(v.z, 0.f); v.w = fmaxf(v.w, 0.f);
        }
        *(float4*)&As[m * KS + 4 * kq] = v;
    }

    const int iw = tid >> 3, nn = (tid & 7) * 4;
    {
        float4 w = *(const float4*)(W + (size_t)(k0 + iw) * N + n0 + nn);
        *(float4*)&Ws[0][iw][nn] = w;
    }
    __syncthreads();

    const int n  = tid & 31;
    const int mb = (tid >> 5) * 8;
    ull acc2[8] = {0,0,0,0,0,0,0,0};

    const int NC = KS / 32;
    for (int c = 0; c < NC; c++) {
        if (c + 1 < NC) {
            float4 w = *(const float4*)(W + (size_t)(k0 + (c+1)*32 + iw) * N + n0 + nn);
            *(float4*)&Ws[(c + 1) & 1][iw][nn] = w;
        }
        const float* wsb = &Ws[c & 1][0][0];
        const int kc = c * 32;
        #pragma unroll
        for (int k = 0; k < 32; k += 4) {
            float w0 = wsb[(k+0)*32 + n], w1 = wsb[(k+1)*32 + n];
            float w2 = wsb[(k+2)*32 + n], w3 = wsb[(k+3)*32 + n];
            ull wA = pk2(w0, w1), wB = pk2(w2, w3);
            #pragma unroll
            for (int q = 0; q < 8; q++) {
                ulonglong2 av = *(const ulonglong2*)&As[(mb + q) * KS + kc + k];
                acc2[q] = fma2(av.x, wA, acc2[q]);
                acc2[q] = fma2(av.y, wB, acc2[q]);
            }
        }
        __syncthreads();
    }

    #pragma unroll
    for (int q = 0; q < 8; q++) {
        float lo, hi; upk2(lo, hi, acc2[q]);
        out[(size_t)(mb + q) * N + n0 + n] = lo + hi;
    }
}

// ---------------------------------------------------------------------------
// ONE fused kernel: 3 MLP phases (persistent, grid barriers) + basis/einsum.
// Grid = 512 blocks x 256 thr; __launch_bounds__(256,4) forces <=64 regs so
// all 512 blocks are co-resident (spin barriers are deadlock-free).
// ---------------------------------------------------------------------------
__global__ void __launch_bounds__(256, 4) fused_all(
    const float* __restrict__ f,  const float* __restrict__ t,
    const float* __restrict__ W1, const float* __restrict__ b1,
    const float* __restrict__ W2, const float* __restrict__ b2,
    const float* __restrict__ W3, const float* __restrict__ b3,
    const float* __restrict__ mu, const float* __restrict__ alpha,
    const float* __restrict__ beta, const float* __restrict__ gamma,
    float* __restrict__ out)
{
    __shared__ float  As[64 * 64];
    __shared__ float  Ws[2][32][32];
    __shared__ float4 s_c1[64];      // (p,p,q,q)
    __shared__ float4 s_c2[64];      // (r,r,beta,beta)
    __shared__ float2 s_c3[64];      // (gamma,gamma)
    __shared__ float4 s_we[64];      // omega even rows: (w0,w1,w2,w3) NON-dup
    __shared__ float4 s_wo[64];      // omega odd rows

    const int bid = blockIdx.x;
    const int tid = threadIdx.x;

    // Phase 1: P1[4] = f @ W1  (N=512, K=128, KS=32) — 64 units
    if (bid < 64) {
        int n0 = (bid & 15) * 32, ks = bid >> 4;
        gemm_tile(As, Ws, f, nullptr, 0, nullptr, 128, 32, W1, 512,
                  n0, ks * 32, g_P1 + (size_t)ks * 64 * 512);
    }
    grid_bar(0);

    // Phase 2: P2[8] = relu(b1 + sum P1) @ W2  (N=1024, K=512, KS=64) — 256 units
    if (bid < 256) {
        int n0 = (bid & 31) * 32, ks = bid >> 5;
        gemm_tile(As, Ws, nullptr, g_P1, 4, b1, 512, 64, W2, 1024,
                  n0, ks * 64, g_P2 + (size_t)ks * 64 * 1024);
    }
    grid_bar(1);

    // Phase 3: P3[16] = relu(b2 + sum P2) @ W3  (N=512, K=1024, KS=64) — 256 units
    if (bid < 256) {
        int n0 = (bid & 15) * 32, ks = bid >> 4;
        gemm_tile(As, Ws, nullptr, g_P2, 8, b2, 1024, 64, W3, 512,
                  n0, ks * 64, g_P3 + (size_t)ks * 64 * 512);
    }
    grid_bar(2);

    // ---- basis + rank-4 einsum + interleave (all 512 blocks) ----
    const int b  = bid >> 3;      // batch
    const int sc = bid & 7;       // s-chunk

    if (tid < 64) {
        float al = alpha[tid], m = mu[tid];
        float a2 = al * al * L2E;
        s_c1[tid] = make_float4(-a2, -a2, 2.f * a2 * m, 2.f * a2 * m);
        float r = -a2 * m * m, be = beta[tid];
        s_c2[tid] = make_float4(r, r, be, be);
        float ga = gamma[tid];
        s_c3[tid] = make_float2(ga, ga);
    }
    // omega[b] = b3 + sum of 16 deterministic split-K partials (non-duplicated)
    for (int j = tid; j < 512; j += 256) {
        float v = b3[j];
        #pragma unroll
        for (int p = 0; p < 16; p++)
            v += g_P3[(size_t)p * 64 * 512 + (size_t)b * 512 + j];
        int row = j >> 2, r = j & 3;
        int nb = row & 63;
        float* dst = (row < 64) ? (float*)&s_we[nb] : (float*)&s_wo[nb];
        dst[r] = v;
    }
    __syncthreads();

    const float* tb = t + (size_t)b * 4096;
    const int s0 = sc * 512 + tid;
    const float t0 = tb[s0], t1 = tb[s0 + 256];
    const ull tt = pk2(t0, t1);
    const ull tq = pk2(t0 * t0, t1 * t1);

    // acc layout: [s-elem][4]: (r0,r1)even, (r2,r3)even, (r0,r1)odd, (r2,r3)odd
    ull acc[8] = {0,0,0,0,0,0,0,0};

    #pragma unroll 4
    for (int nb = 0; nb < 64; nb++) {
        ulonglong2 c1 = *(const ulonglong2*)&s_c1[nb];  // (p,p)(q,q)
        ulonglong2 c2 = *(const ulonglong2*)&s_c2[nb];  // (r,r)(b,b)
        ull gg = *(const ull*)&s_c3[nb];                // (g,g)
        ulonglong2 we = *(const ulonglong2*)&s_we[nb];  // (w0,w1)(w2,w3) even
        ulonglong2 wo = *(const ulonglong2*)&s_wo[nb];  // odd

        ull a = fma2(c1.x, tq, fma2(c1.y, tt, c2.x));   // s-packed poly
        float a0, a1; upk2(a0, a1, a);
        float e0, e1;
        asm("ex2.approx.f32 %0, %1;" : "=f"(e0) : "f"(a0));
        asm("ex2.approx.f32 %0, %1;" : "=f"(e1) : "f"(a1));

        ull ca = fma2(c2.y, tt, gg);                    // s-packed cos arg
        float c0, c1f; upk2(c0, c1f, ca);
        float h0 = e0 * __cosf(c0);
        float h1 = e1 * __cosf(c1f);
        ull hh0 = pk2(h0, h0), hh1 = pk2(h1, h1);

        acc[0] = fma2(hh0, we.x, acc[0]);
        acc[1] = fma2(hh0, we.y, acc[1]);
        acc[2] = fma2(hh0, wo.x, acc[2]);
        acc[3] = fma2(hh0, wo.y, acc[3]);
        acc[4] = fma2(hh1, we.x, acc[4]);
        acc[5] = fma2(hh1, we.y, acc[5]);
        acc[6] = fma2(hh1, wo.x, acc[6]);
        acc[7] = fma2(hh1, wo.y, acc[7]);
    }

    float* ob = out + (size_t)b * 32768;
    {
        float r0, r1, r2, r3, q0, q1, q2, q3;
        upk2(r0, r1, acc[0]); upk2(r2, r3, acc[1]);
        upk2(q0, q1, acc[2]); upk2(q2, q3, acc[3]);
        float4* o = reinterpret_cast<float4*>(ob + 8 * (size_t)s0);
        o[0] = make_float4(r0, r1, r2, r3);
        o[1] = make_float4(q0, q1, q2, q3);
    }
    {
        float r0, r1, r2, r3, q0, q1, q2, q3;
        upk2(r0, r1, acc[4]); upk2(r2, r3, acc[5]);
        upk2(q0, q1, acc[6]); upk2(q2, q3, acc[7]);
        float4* o = reinterpret_cast<float4*>(ob + 8 * (size_t)(s0 + 256));
        o[0] = make_float4(r0, r1, r2, r3);
        o[1] = make_float4(q0, q1, q2, q3);
    }
}

extern "C" void kernel_launch(void* const* d_in, const int* in_sizes, int n_in,
                              void* d_out, int out_size) {
    const float* f     = (const float*)d_in[0];
    const float* t     = (const float*)d_in[1];
    const float* W1    = (const float*)d_in[2];
    const float* b1    = (const float*)d_in[3];
    const float* W2    = (const float*)d_in[4];
    const float* b2    = (const float*)d_in[5];
    const float* W3    = (const float*)d_in[6];
    const float* b3    = (const float*)d_in[7];
    const float* mu    = (const float*)d_in[8];
    const float* alpha = (const float*)d_in[9];
    const float* beta  = (const float*)d_in[10];
    const float* gamma = (const float*)d_in[11];
    float* out = (float*)d_out;

    fused_all<<<512, 256>>>(f, t, W1, b1, W2, b2, W3, b3,
                            mu, alpha, beta, gamma, out);
}